// round 5
// baseline (speedup 1.0000x reference)
#include <cuda_runtime.h>

// Problem constants
#define TT   1024   // seq len
#define BB   1024   // batch
#define HH   64     // encoder hidden
#define NB   7      // batch elements per CTA
#define CTAS 147    // 147*7 = 1029 >= 1024

// ---------------------------------------------------------------------------
// helpers
// ---------------------------------------------------------------------------
__device__ __forceinline__ void ffma2(unsigned long long &d,
                                      unsigned long long a,
                                      unsigned long long b) {
    asm("fma.rn.f32x2 %0, %1, %2, %0;" : "+l"(d) : "l"(a), "l"(b));
}
__device__ __forceinline__ unsigned long long packf2(float lo, float hi) {
    unsigned long long r;
    asm("mov.b64 %0, {%1,%2};" : "=l"(r) : "f"(lo), "f"(hi));
    return r;
}
__device__ __forceinline__ float ex2f(float x) {
    float r; asm("ex2.approx.f32 %0, %1;" : "=f"(r) : "f"(x)); return r;
}
__device__ __forceinline__ float rcpf(float x) {
    float r; asm("rcp.approx.f32 %0, %1;" : "=f"(r) : "f"(x)); return r;
}

#define L2E      1.4426950408889634f
#define TWO_L2E  2.8853900817779268f

__device__ __forceinline__ float tanhx(float x) {      // rel err ~1e-7
    return fmaf(-2.0f, rcpf(1.0f + ex2f(TWO_L2E * x)), 1.0f);
}

// k-interleaved slot for h storage: k = khalf*32 + kk*4 + e
//  -> slot = kk*8 + khalf*4 + e   (both k-halves' float4 chunks adjacent)
__device__ __forceinline__ int hslot(int k) {
    return (((k & 31) >> 2) << 3) + ((k >> 5) << 2) + (k & 3);
}

// ---------------------------------------------------------------------------
// Fused encoder+decoder, K-split. 147 CTAs x 512 threads; NB=7 chains/CTA.
//
// Thread layout:
//   sub   = tid>>8        (2 subgroups; batches {0..3} / {4..6})
//   half  = tid&1         (gate pair: 0 -> rows (i,f)=(j, j+64);
//                                     1 -> rows (g,o)=(j+128, j+192))
//   khalf = (tid>>1)&1    (k range [khalf*32, khalf*32+32))
//   j     = (tid&255)>>2  (hidden index 0..63)
// Each thread: 2 gate rows x 32 k of Whh in regs (32 packed f32x2).
// -> 16 warps/CTA = 4 warps/SMSP for latency hiding; FMA floor 896 cyc/step.
// h stored k-interleaved so the warp's two k-half addresses are 16B apart
// (one LDS wavefront). Epilogue: shfl_xor(2) k-combine; each lane computes
// ONE activation (unified per-lane A,B constants: sigmoid or tanh) and
// shfl_xor(2) exchanges it; shfl_xor(1) exchanges the gate pair; all lanes
// keep c; lane (tid&3)==0 stores h. One per-subgroup named barrier per step.
// Decoder (hidden=1) fused at the end, reading h via the slot permutation.
// ---------------------------------------------------------------------------
__global__ void __launch_bounds__(512, 1) fused_kernel(
    const float* __restrict__ x,      // [T, B, 1]
    const float* __restrict__ Wih,    // [256, 1]
    const float* __restrict__ Whh,    // [256, 64]
    const float* __restrict__ bih,    // [256]
    const float* __restrict__ bhh,    // [256]
    const float* __restrict__ Wih_d,  // [4, 64]
    const float* __restrict__ Whh_d,  // [4, 1]
    const float* __restrict__ bih_d,  // [4]
    const float* __restrict__ bhh_d,  // [4]
    float* __restrict__ out)          // [T, B, 1]
{
    const int tid   = threadIdx.x;
    const int sub   = tid >> 8;
    const int half  = tid & 1;
    const int khalf = (tid >> 1) & 1;
    const int j     = (tid & 255) >> 2;
    const int r0    = half * 128 + j;       // i (half0) / g (half1)
    const int r1    = r0 + 64;              // f (half0) / o (half1)
    const int ko    = khalf * 32;
    const int b0    = blockIdx.x * NB;
    const int nb     = sub ? 3 : 4;
    const int b_base = sub ? 4 : 0;
    const int jslot  = hslot(j);

    __shared__ __align__(16) float hs[2][NB][HH];

    // row scales (folded into weights/bias): r0 = i(sig)/g(tanh), r1 = f/o(sig)
    const float s0 = half ? TWO_L2E : -L2E;
    const float s1 = -L2E;
    // my activation (khalf0 -> row r0, khalf1 -> row r1); tanh only for g
    const bool  tm = (half == 1) && (khalf == 0);
    const float Am = tm ? -2.0f : 1.0f;
    const float Bm = tm ?  1.0f : 0.0f;

    // weights: my 32 k-values of both rows, pre-scaled, packed over k
    unsigned long long w0[16], w1[16];
    {
        const float2* p0 = (const float2*)(Whh + r0 * HH + ko);
        const float2* p1 = (const float2*)(Whh + r1 * HH + ko);
        #pragma unroll
        for (int i = 0; i < 16; i++) {
            float2 v0 = p0[i], v1 = p1[i];
            w0[i] = packf2(v0.x * s0, v0.y * s0);
            w1[i] = packf2(v1.x * s1, v1.y * s1);
        }
    }
    // bias + input coeffs only on khalf==0 (k-combine sums both partials)
    const float be0  = khalf ? 0.0f : s0 * (bih[r0] + bhh[r0]);
    const float be1  = khalf ? 0.0f : s1 * (bih[r1] + bhh[r1]);
    const float wih0 = khalf ? 0.0f : s0 * Wih[r0];
    const float wih1 = khalf ? 0.0f : s1 * Wih[r1];

    // batch offsets (clamped duplicates are deterministic)
    int off[4];
    #pragma unroll
    for (int bi = 0; bi < 4; bi++) {
        int gb = b0 + b_base + bi; if (gb > BB - 1) gb = BB - 1;
        off[bi] = gb;
    }
    float xv[4];
    #pragma unroll
    for (int bi = 0; bi < 4; bi++) if (bi < nb) xv[bi] = __ldg(x + off[bi]);

    for (int i = tid; i < NB * HH; i += 512) ((float*)hs[0])[i] = 0.0f;
    float cc[4] = {0.0f, 0.0f, 0.0f, 0.0f};
    __syncthreads();

    const float* xt = x + BB;   // next step's x row

    for (int t = 0; t < TT; t++) {
        const float* __restrict__ hr = hs[t & 1][0];
        float* __restrict__       hw = hs[(t + 1) & 1][0];

        // accumulator init: bias + input term (this step's x)
        unsigned long long a0[4], a1[4];
        #pragma unroll
        for (int bi = 0; bi < 4; bi++) if (bi < nb) {
            a0[bi] = packf2(fmaf(wih0, xv[bi], be0), 0.0f);
            a1[bi] = packf2(fmaf(wih1, xv[bi], be1), 0.0f);
        }
        // prefetch next x under the matvec
        if (t + 1 < TT) {
            #pragma unroll
            for (int bi = 0; bi < 4; bi++)
                if (bi < nb) xv[bi] = __ldg(xt + off[bi]);
        }

        // ---- matvec: my 32 k of all batches ----
        #pragma unroll
        for (int kk = 0; kk < 8; kk++) {
            #pragma unroll
            for (int bi = 0; bi < 4; bi++) if (bi < nb) {
                ulonglong2 h4 = ((const ulonglong2*)
                    (hr + (b_base + bi) * HH))[2 * kk + khalf];
                ffma2(a0[bi], w0[2 * kk],     h4.x);
                ffma2(a0[bi], w0[2 * kk + 1], h4.y);
                ffma2(a1[bi], w1[2 * kk],     h4.x);
                ffma2(a1[bi], w1[2 * kk + 1], h4.y);
            }
        }

        // ---- epilogue ----
        #pragma unroll
        for (int bi = 0; bi < 4; bi++) if (bi < nb) {
            float l0, h0, l1, h1;
            asm("mov.b64 {%0,%1}, %2;" : "=f"(l0), "=f"(h0) : "l"(a0[bi]));
            asm("mov.b64 {%0,%1}, %2;" : "=f"(l1), "=f"(h1) : "l"(a1[bi]));
            float sA = l0 + h0, sB = l1 + h1;
            sA += __shfl_xor_sync(0xffffffffu, sA, 2);   // k-combine row r0
            sB += __shfl_xor_sync(0xffffffffu, sB, 2);   // k-combine row r1
            // one activation per lane (khalf0 -> r0, khalf1 -> r1)
            float sm = khalf ? sB : sA;
            float am = fmaf(Am, rcpf(1.0f + ex2f(sm)), Bm);
            float ax = __shfl_xor_sync(0xffffffffu, am, 2);  // partner's act
            float aR0 = khalf ? ax : am;
            float aR1 = khalf ? am : ax;
            float pR0 = __shfl_xor_sync(0xffffffffu, aR0, 1); // i<->g
            float pR1 = __shfl_xor_sync(0xffffffffu, aR1, 1); // f<->o
            float ai = half ? pR0 : aR0;
            float ag = half ? aR0 : pR0;
            float af = half ? pR1 : aR1;
            float ao = half ? aR1 : pR1;
            cc[bi] = fmaf(af, cc[bi], ai * ag);
            float hn = ao * tanhx(cc[bi]);
            if ((tid & 3) == 0)
                hw[(b_base + bi) * HH + jslot] = hn;
        }

        // per-subgroup barrier (hs is subgroup-private) -> subgroups drift
        asm volatile("bar.sync %0, %1;" :: "r"(sub + 1), "r"(256) : "memory");
        xt += BB;
    }
    // final h in hs[0] (t=1023 wrote buffer (1024)&1 = 0)
    __syncthreads();   // decoder reads both subgroups' batches

    // ------------------- fused decoder (7 threads per CTA) -------------------
    if (tid < NB) {
        const int gb = b0 + tid;
        if (gb < BB) {
            const float* he = hs[0][tid];
            float z[4], w[4];
            #pragma unroll
            for (int g = 0; g < 4; g++) {
                float acc = bih_d[g] + bhh_d[g];
                const float* wr = Wih_d + g * HH;
                #pragma unroll
                for (int k = 0; k < HH; k++)
                    acc = fmaf(wr[k], he[hslot(k)], acc);
                const float s = (g == 2) ? TWO_L2E : -L2E;
                z[g] = s * acc;
                w[g] = s * Whh_d[g];
            }
            float h = 0.0f, c = 0.0f;
            float* op = out + gb;
            for (int t = 0; t < TT; t++) {
                float gi = fmaf(w[0], h, z[0]);
                float gf = fmaf(w[1], h, z[1]);
                float gg = fmaf(w[2], h, z[2]);
                float go = fmaf(w[3], h, z[3]);
                float ai = rcpf(1.0f + ex2f(gi));
                float af = rcpf(1.0f + ex2f(gf));
                float ag = fmaf(-2.0f, rcpf(1.0f + ex2f(gg)), 1.0f);
                float ao = rcpf(1.0f + ex2f(go));
                c = fmaf(af, c, ai * ag);
                h = ao * tanhx(c);
                *op = h;
                op += BB;
            }
        }
    }
}

// ---------------------------------------------------------------------------
// launch
// ---------------------------------------------------------------------------
extern "C" void kernel_launch(void* const* d_in, const int* in_sizes, int n_in,
                              void* d_out, int out_size) {
    const float* x     = (const float*)d_in[0];
    const float* Wih_e = (const float*)d_in[1];
    const float* Whh_e = (const float*)d_in[2];
    const float* bih_e = (const float*)d_in[3];
    const float* bhh_e = (const float*)d_in[4];
    const float* Wih_d = (const float*)d_in[5];
    const float* Whh_d = (const float*)d_in[6];
    const float* bih_d = (const float*)d_in[7];
    const float* bhh_d = (const float*)d_in[8];
    float* out = (float*)d_out;

    fused_kernel<<<CTAS, 512>>>(x, Wih_e, Whh_e, bih_e, bhh_e,
                                Wih_d, Whh_d, bih_d, bhh_d, out);
}